// round 7
// baseline (speedup 1.0000x reference)
#include <cuda_runtime.h>
#include <cstdint>

// PowerSpectrum: values[S,N,L,M,Q] f32 -> out[S,N,L*Q*Q] f32
// out[s,n,l,q,p] = rsqrt(2l+1) * sum_{m<2l+1} v[m,q]*v[m,p]
// Shapes: S=4, N=2000, L=4, M=7, Q=64.
//
// R4/R5 plateau at ~6.0 TB/s DRAM with L1tex at 61% (LDS+STG share the
// l1tex wavefront queue). R6: 8x8 per-thread register tile -> LDS drops
// to 1 B/FFMA; 64 threads cover one full 64x64 tile. 128-thread CTA per
// (s,n): half A does l=0 (1m) + l=3 (7m), half B does l=1 (3m) + l=2
// (5m) -- 8 m-iters each, no trailing sync.

#define L_DIM 4
#define M_DIM 7
#define Q_DIM 64
#define TILE_IN   (M_DIM * Q_DIM)          // 448 floats per (s,n,l)
#define TILE_OUT  (Q_DIM * Q_DIM)          // 4096 floats per (s,n,l)
#define GROUP_IN  (L_DIM * TILE_IN)        // 1792 floats per (s,n)
#define GROUP_OUT (L_DIM * TILE_OUT)       // 16384 floats per (s,n)

// t in [0,64): 8 q-groups x 8 p-groups, each thread owns an 8x8 block.
template<int MM>
__device__ __forceinline__ void gram8x8(const float (*__restrict__ sv)[Q_DIM],
                                        float* __restrict__ ot, int t)
{
    const int q0 = (t >> 3) << 3;   // 0,8,...,56
    const int p0 = (t & 7)  << 3;   // 0,8,...,56

    const float cg = rsqrtf((float)MM);

    float4 acc[8][2];
    #pragma unroll
    for (int r = 0; r < 8; r++) {
        acc[r][0] = make_float4(0.f, 0.f, 0.f, 0.f);
        acc[r][1] = make_float4(0.f, 0.f, 0.f, 0.f);
    }

    #pragma unroll
    for (int m = 0; m < MM; m++) {
        const float4 b0 = *(const float4*)&sv[m][p0];
        const float4 b1 = *(const float4*)&sv[m][p0 + 4];
        const float4 a0 = *(const float4*)&sv[m][q0];
        const float4 a1 = *(const float4*)&sv[m][q0 + 4];
        const float ar[8] = {a0.x, a0.y, a0.z, a0.w, a1.x, a1.y, a1.z, a1.w};
        #pragma unroll
        for (int r = 0; r < 8; r++) {
            acc[r][0].x += ar[r] * b0.x;
            acc[r][0].y += ar[r] * b0.y;
            acc[r][0].z += ar[r] * b0.z;
            acc[r][0].w += ar[r] * b0.w;
            acc[r][1].x += ar[r] * b1.x;
            acc[r][1].y += ar[r] * b1.y;
            acc[r][1].z += ar[r] * b1.z;
            acc[r][1].w += ar[r] * b1.w;
        }
    }

    // Streaming stores: the 8 lanes sharing a q-group jointly cover each
    // full 256B output row (8 lanes x 2 x 16B, interleaved). Coalesced.
    #pragma unroll
    for (int r = 0; r < 8; r++) {
        float* row = ot + (size_t)(q0 + r) * Q_DIM + p0;
        float4 o0 = make_float4(acc[r][0].x * cg, acc[r][0].y * cg,
                                acc[r][0].z * cg, acc[r][0].w * cg);
        float4 o1 = make_float4(acc[r][1].x * cg, acc[r][1].y * cg,
                                acc[r][1].z * cg, acc[r][1].w * cg);
        __stcs((float4*)row, o0);
        __stcs((float4*)(row + 4), o1);
    }
}

__global__ __launch_bounds__(128)
void powerspectrum_kernel(const float* __restrict__ values,
                          float* __restrict__ out)
{
    const int grp = blockIdx.x;            // (s*N + n)
    const float* vt = values + (size_t)grp * GROUP_IN;
    float*       ot = out    + (size_t)grp * GROUP_OUT;

    __shared__ float sv[L_DIM][M_DIM][Q_DIM];   // 7168 B

    const int tid = threadIdx.x;

    // Coalesced group load: 448 float4 across 128 threads.
    const float4* src = (const float4*)vt;
    float4*       dst = (float4*)&sv[0][0][0];
    #pragma unroll
    for (int i = tid; i < GROUP_IN / 4; i += 128)
        dst[i] = src[i];
    __syncthreads();

    const int t = tid & 63;
    if (tid < 64) {
        // half A: l=0 (1 m-iter) + l=3 (7 m-iters) = 8
        gram8x8<1>(sv[0], ot + 0 * TILE_OUT, t);
        gram8x8<7>(sv[3], ot + 3 * TILE_OUT, t);
    } else {
        // half B: l=1 (3) + l=2 (5) = 8
        gram8x8<3>(sv[1], ot + 1 * TILE_OUT, t);
        gram8x8<5>(sv[2], ot + 2 * TILE_OUT, t);
    }
}

extern "C" void kernel_launch(void* const* d_in, const int* in_sizes, int n_in,
                              void* d_out, int out_size)
{
    const float* values = (const float*)d_in[0];
    float* out = (float*)d_out;

    const int groups = in_sizes[0] / GROUP_IN;   // S*N = 8000

    powerspectrum_kernel<<<groups, 128>>>(values, out);
}

// round 8
// speedup vs baseline: 1.3794x; 1.3794x over previous
#include <cuda_runtime.h>
#include <cstdint>

// PowerSpectrum: values[S,N,L,M,Q] f32 -> out[S,N,L*Q*Q] f32
// out[s,n,l,q,p] = rsqrt(2l+1) * sum_{m<2l+1} v[m,q]*v[m,p]
// Shapes: S=4, N=2000, L=4, M=7, Q=64 -> 32000 (s,n,l) tiles.
//
// Best known: R4 (88.5us, DRAM 76.4%, occ 39.3%, regs 66): one CTA per
// tile, 8x4 per-thread register block, compile-time m-count, streaming
// stores. R6 (8x8 tile) proved occupancy x store-MLP is the binding
// product. R8 = R4 + __launch_bounds__(128, 8): cap regs at 64 so the SM
// fits 8 CTAs (occ 50%) instead of 7, raising concurrent store streams.

#define L_DIM 4
#define M_DIM 7
#define Q_DIM 64
#define TILE_IN   (M_DIM * Q_DIM)   // 448 floats
#define TILE_OUT  (Q_DIM * Q_DIM)   // 4096 floats

template<int MM>
__device__ __forceinline__ void gram_tile(const float (*__restrict__ sv)[Q_DIM],
                                          float* __restrict__ ot, int tid)
{
    const int p0 = (tid & 15) << 2;  // 0,4,...,60
    const int q0 = (tid >> 4) << 3;  // 0,8,...,56

    const float cg = rsqrtf((float)MM);

    float4 acc[8];
    #pragma unroll
    for (int r = 0; r < 8; r++) acc[r] = make_float4(0.f, 0.f, 0.f, 0.f);

    #pragma unroll
    for (int m = 0; m < MM; m++) {
        const float4 b  = *(const float4*)&sv[m][p0];
        const float4 a0 = *(const float4*)&sv[m][q0];
        const float4 a1 = *(const float4*)&sv[m][q0 + 4];
        const float ar[8] = {a0.x, a0.y, a0.z, a0.w, a1.x, a1.y, a1.z, a1.w};
        #pragma unroll
        for (int r = 0; r < 8; r++) {
            acc[r].x += ar[r] * b.x;
            acc[r].y += ar[r] * b.y;
            acc[r].z += ar[r] * b.z;
            acc[r].w += ar[r] * b.w;
        }
    }

    // Streaming stores: 16 threads (same q-group) cover one full 256B
    // output row; fully coalesced. 8 independent STG.128 per thread.
    #pragma unroll
    for (int r = 0; r < 8; r++) {
        float4 o = make_float4(acc[r].x * cg, acc[r].y * cg,
                               acc[r].z * cg, acc[r].w * cg);
        __stcs((float4*)(ot + (size_t)(q0 + r) * Q_DIM + p0), o);
    }
}

__global__ __launch_bounds__(128, 8)
void powerspectrum_kernel(const float* __restrict__ values,
                          float* __restrict__ out)
{
    const int tile = blockIdx.x;           // tile = (s*N + n)*L + l
    const int l    = tile & (L_DIM - 1);

    const float* vt = values + (size_t)tile * TILE_IN;
    float*       ot = out    + (size_t)tile * TILE_OUT;

    __shared__ float sv[M_DIM][Q_DIM];     // 1792 B

    const int tid = threadIdx.x;

    // 448 floats = 112 float4 loads; threads 0..111
    if (tid < TILE_IN / 4)
        ((float4*)&sv[0][0])[tid] = ((const float4*)vt)[tid];
    __syncthreads();

    switch (l) {
        case 0: gram_tile<1>(sv, ot, tid); break;
        case 1: gram_tile<3>(sv, ot, tid); break;
        case 2: gram_tile<5>(sv, ot, tid); break;
        default: gram_tile<7>(sv, ot, tid); break;
    }
}

extern "C" void kernel_launch(void* const* d_in, const int* in_sizes, int n_in,
                              void* d_out, int out_size)
{
    const float* values = (const float*)d_in[0];
    float* out = (float*)d_out;

    const int tiles = in_sizes[0] / TILE_IN;   // S*N*L = 32000

    powerspectrum_kernel<<<tiles, 128>>>(values, out);
}

// round 9
// speedup vs baseline: 1.3843x; 1.0035x over previous
#include <cuda_runtime.h>
#include <cstdint>

// PowerSpectrum: values[S,N,L,M,Q] f32 -> out[S,N,L*Q*Q] f32
// out[s,n,l,q,p] = rsqrt(2l+1) * sum_{m<2l+1} v[m,q]*v[m,p]
// Shapes: S=4, N=2000, L=4, M=7, Q=64 -> 32000 (s,n,l) tiles.
//
// R4/R5/R8 all pin DRAM at ~6.0 TB/s regardless of occupancy/CTA shape.
// R9 tests the store path: stage the 16KB tile in SMEM, then emit ONE
// contiguous cp.async.bulk shared->global per CTA (TMA bulk store) for
// maximal DRAM page locality and zero STG traffic through L1tex.

#define L_DIM 4
#define M_DIM 7
#define Q_DIM 64
#define TILE_IN   (M_DIM * Q_DIM)   // 448 floats
#define TILE_OUT  (Q_DIM * Q_DIM)   // 4096 floats = 16384 bytes

template<int MM>
__device__ __forceinline__ void gram_tile(const float (*__restrict__ sv)[Q_DIM],
                                          float (*__restrict__ so)[Q_DIM],
                                          int tid)
{
    const int p0 = (tid & 15) << 2;  // 0,4,...,60
    const int q0 = (tid >> 4) << 3;  // 0,8,...,56

    const float cg = rsqrtf((float)MM);

    float4 acc[8];
    #pragma unroll
    for (int r = 0; r < 8; r++) acc[r] = make_float4(0.f, 0.f, 0.f, 0.f);

    #pragma unroll
    for (int m = 0; m < MM; m++) {
        const float4 b  = *(const float4*)&sv[m][p0];
        const float4 a0 = *(const float4*)&sv[m][q0];
        const float4 a1 = *(const float4*)&sv[m][q0 + 4];
        const float ar[8] = {a0.x, a0.y, a0.z, a0.w, a1.x, a1.y, a1.z, a1.w};
        #pragma unroll
        for (int r = 0; r < 8; r++) {
            acc[r].x += ar[r] * b.x;
            acc[r].y += ar[r] * b.y;
            acc[r].z += ar[r] * b.z;
            acc[r].w += ar[r] * b.w;
        }
    }

    // Stage to SMEM (conflict-light: 16 threads per row, float4 lanes).
    #pragma unroll
    for (int r = 0; r < 8; r++) {
        float4 o = make_float4(acc[r].x * cg, acc[r].y * cg,
                               acc[r].z * cg, acc[r].w * cg);
        *(float4*)&so[q0 + r][p0] = o;
    }
}

__global__ __launch_bounds__(128)
void powerspectrum_kernel(const float* __restrict__ values,
                          float* __restrict__ out)
{
    const int tile = blockIdx.x;           // tile = (s*N + n)*L + l
    const int l    = tile & (L_DIM - 1);

    const float* vt = values + (size_t)tile * TILE_IN;
    float*       ot = out    + (size_t)tile * TILE_OUT;

    __shared__ float sv[M_DIM][Q_DIM];               // 1792 B
    __shared__ __align__(16) float so[Q_DIM][Q_DIM]; // 16384 B staging

    const int tid = threadIdx.x;

    // 448 floats = 112 float4 loads; threads 0..111
    if (tid < TILE_IN / 4)
        ((float4*)&sv[0][0])[tid] = ((const float4*)vt)[tid];
    __syncthreads();

    switch (l) {
        case 0: gram_tile<1>(sv, so, tid); break;
        case 1: gram_tile<3>(sv, so, tid); break;
        case 2: gram_tile<5>(sv, so, tid); break;
        default: gram_tile<7>(sv, so, tid); break;
    }
    __syncthreads();

    // One contiguous 16KB bulk store per CTA (shared -> global).
    if (tid == 0) {
        // order generic-proxy STS before async-proxy bulk read
        asm volatile("fence.proxy.async.shared::cta;" ::: "memory");
        uint32_t s_addr;
        asm("{ .reg .u64 t; cvta.to.shared.u64 t, %1; cvt.u32.u64 %0, t; }"
            : "=r"(s_addr) : "l"(&so[0][0]));
        asm volatile(
            "cp.async.bulk.global.shared::cta.bulk_group [%0], [%1], %2;"
            :: "l"(ot), "r"(s_addr), "r"(TILE_OUT * 4) : "memory");
        asm volatile("cp.async.bulk.commit_group;" ::: "memory");
        // SMEM must stay live until the bulk read completes.
        asm volatile("cp.async.bulk.wait_group.read 0;" ::: "memory");
    }
}

extern "C" void kernel_launch(void* const* d_in, const int* in_sizes, int n_in,
                              void* d_out, int out_size)
{
    const float* values = (const float*)d_in[0];
    float* out = (float*)d_out;

    const int tiles = in_sizes[0] / TILE_IN;   // S*N*L = 32000

    powerspectrum_kernel<<<tiles, 128>>>(values, out);
}

// round 10
// speedup vs baseline: 1.4052x; 1.0151x over previous
#include <cuda_runtime.h>
#include <cstdint>

// PowerSpectrum: values[S,N,L,M,Q] f32 -> out[S,N,L*Q*Q] f32
// out[s,n,l,q,p] = rsqrt(2l+1) * sum_{m<2l+1} v[m,q]*v[m,p]
// Shapes: S=4, N=2000, L=4, M=7, Q=64 -> 32000 (s,n,l) tiles.
//
// FINAL (R4 design, best measured: 88.5us, DRAM 76.4%, HBM 6.05TB/s).
// The kernel is write-BW bound: 524MB compulsory f32 output. Experiments
// R5 (CTA merging), R6 (8x8 tile), R8 (occupancy cap), R9 (TMA bulk
// store) all proved ~6.0TB/s is the path-independent HBM ceiling for
// this stream; R4's shape is the fastest of the roofline cluster.
//
// Design: one CTA per (s,n,l) tile. 1.8KB input to SMEM, 8x4 per-thread
// register block (1.5 B LDS per FFMA), compile-time m-count per l
// (1/3/5/7 -- invalid m rows never touched), streaming STG.128 stores
// (write-once output kept out of L2's working set), fully coalesced
// 256B row segments.

#define L_DIM 4
#define M_DIM 7
#define Q_DIM 64
#define TILE_IN   (M_DIM * Q_DIM)   // 448 floats
#define TILE_OUT  (Q_DIM * Q_DIM)   // 4096 floats

template<int MM>
__device__ __forceinline__ void gram_tile(const float (*__restrict__ sv)[Q_DIM],
                                          float* __restrict__ ot, int tid)
{
    const int p0 = (tid & 15) << 2;  // 0,4,...,60
    const int q0 = (tid >> 4) << 3;  // 0,8,...,56

    const float cg = rsqrtf((float)MM);

    float4 acc[8];
    #pragma unroll
    for (int r = 0; r < 8; r++) acc[r] = make_float4(0.f, 0.f, 0.f, 0.f);

    #pragma unroll
    for (int m = 0; m < MM; m++) {
        const float4 b  = *(const float4*)&sv[m][p0];
        const float4 a0 = *(const float4*)&sv[m][q0];
        const float4 a1 = *(const float4*)&sv[m][q0 + 4];
        const float ar[8] = {a0.x, a0.y, a0.z, a0.w, a1.x, a1.y, a1.z, a1.w};
        #pragma unroll
        for (int r = 0; r < 8; r++) {
            acc[r].x += ar[r] * b.x;
            acc[r].y += ar[r] * b.y;
            acc[r].z += ar[r] * b.z;
            acc[r].w += ar[r] * b.w;
        }
    }

    // Streaming stores: 16 threads (same q-group) cover one full 256B
    // output row; fully coalesced. 8 independent STG.128 per thread.
    #pragma unroll
    for (int r = 0; r < 8; r++) {
        float4 o = make_float4(acc[r].x * cg, acc[r].y * cg,
                               acc[r].z * cg, acc[r].w * cg);
        __stcs((float4*)(ot + (size_t)(q0 + r) * Q_DIM + p0), o);
    }
}

__global__ __launch_bounds__(128)
void powerspectrum_kernel(const float* __restrict__ values,
                          float* __restrict__ out)
{
    const int tile = blockIdx.x;           // tile = (s*N + n)*L + l
    const int l    = tile & (L_DIM - 1);

    const float* vt = values + (size_t)tile * TILE_IN;
    float*       ot = out    + (size_t)tile * TILE_OUT;

    __shared__ float sv[M_DIM][Q_DIM];     // 1792 B

    const int tid = threadIdx.x;

    // 448 floats = 112 float4 loads; threads 0..111
    if (tid < TILE_IN / 4)
        ((float4*)&sv[0][0])[tid] = ((const float4*)vt)[tid];
    __syncthreads();

    switch (l) {
        case 0: gram_tile<1>(sv, ot, tid); break;
        case 1: gram_tile<3>(sv, ot, tid); break;
        case 2: gram_tile<5>(sv, ot, tid); break;
        default: gram_tile<7>(sv, ot, tid); break;
    }
}

extern "C" void kernel_launch(void* const* d_in, const int* in_sizes, int n_in,
                              void* d_out, int out_size)
{
    const float* values = (const float*)d_in[0];
    float* out = (float*)d_out;

    const int tiles = in_sizes[0] / TILE_IN;   // S*N*L = 32000

    powerspectrum_kernel<<<tiles, 128>>>(values, out);
}

// round 11
// speedup vs baseline: 1.4072x; 1.0014x over previous
#include <cuda_runtime.h>
#include <cstdint>

// PowerSpectrum: values[S,N,L,M,Q] f32 -> out[S,N,L*Q*Q] f32
// out[s,n,l,q,p] = rsqrt(2l+1) * sum_{m<2l+1} v[m,q]*v[m,p]
// Shapes: S=4, N=2000, L=4, M=7, Q=64 -> 32000 (s,n,l) tiles.
//
// FINAL (R4 design; best measured 88.5us bench / 85.6us ncu, DRAM 76.9%,
// HBM 6.09TB/s). Write-BW bound: 524MB compulsory f32 output drains as a
// pure write stream (input stays L2-resident across replays). Controlled
// experiments -- R5 CTA merging, R6 8x8 tile, R8 occupancy cap, R9 TMA
// bulk store -- all pinned DRAM at ~6.0-6.1TB/s: the path-independent
// HBM ceiling for this stream. No kernel-addressable headroom remains.
//
// Design: one CTA per (s,n,l) tile. 1.8KB input to SMEM, 8x4 per-thread
// register block (1.5 B LDS per FFMA), compile-time m-count per l
// (1/3/5/7 -- invalid m rows never touched), streaming STG.128 stores
// (.cs keeps the write-once output from evicting the L2-resident input),
// fully coalesced 256B row segments.

#define L_DIM 4
#define M_DIM 7
#define Q_DIM 64
#define TILE_IN   (M_DIM * Q_DIM)   // 448 floats
#define TILE_OUT  (Q_DIM * Q_DIM)   // 4096 floats

template<int MM>
__device__ __forceinline__ void gram_tile(const float (*__restrict__ sv)[Q_DIM],
                                          float* __restrict__ ot, int tid)
{
    const int p0 = (tid & 15) << 2;  // 0,4,...,60
    const int q0 = (tid >> 4) << 3;  // 0,8,...,56

    const float cg = rsqrtf((float)MM);

    float4 acc[8];
    #pragma unroll
    for (int r = 0; r < 8; r++) acc[r] = make_float4(0.f, 0.f, 0.f, 0.f);

    #pragma unroll
    for (int m = 0; m < MM; m++) {
        const float4 b  = *(const float4*)&sv[m][p0];
        const float4 a0 = *(const float4*)&sv[m][q0];
        const float4 a1 = *(const float4*)&sv[m][q0 + 4];
        const float ar[8] = {a0.x, a0.y, a0.z, a0.w, a1.x, a1.y, a1.z, a1.w};
        #pragma unroll
        for (int r = 0; r < 8; r++) {
            acc[r].x += ar[r] * b.x;
            acc[r].y += ar[r] * b.y;
            acc[r].z += ar[r] * b.z;
            acc[r].w += ar[r] * b.w;
        }
    }

    // Streaming stores: 16 threads (same q-group) cover one full 256B
    // output row; fully coalesced. 8 independent STG.128 per thread.
    #pragma unroll
    for (int r = 0; r < 8; r++) {
        float4 o = make_float4(acc[r].x * cg, acc[r].y * cg,
                               acc[r].z * cg, acc[r].w * cg);
        __stcs((float4*)(ot + (size_t)(q0 + r) * Q_DIM + p0), o);
    }
}

__global__ __launch_bounds__(128)
void powerspectrum_kernel(const float* __restrict__ values,
                          float* __restrict__ out)
{
    const int tile = blockIdx.x;           // tile = (s*N + n)*L + l
    const int l    = tile & (L_DIM - 1);

    const float* vt = values + (size_t)tile * TILE_IN;
    float*       ot = out    + (size_t)tile * TILE_OUT;

    __shared__ float sv[M_DIM][Q_DIM];     // 1792 B

    const int tid = threadIdx.x;

    // 448 floats = 112 float4 loads; threads 0..111
    if (tid < TILE_IN / 4)
        ((float4*)&sv[0][0])[tid] = ((const float4*)vt)[tid];
    __syncthreads();

    switch (l) {
        case 0: gram_tile<1>(sv, ot, tid); break;
        case 1: gram_tile<3>(sv, ot, tid); break;
        case 2: gram_tile<5>(sv, ot, tid); break;
        default: gram_tile<7>(sv, ot, tid); break;
    }
}

extern "C" void kernel_launch(void* const* d_in, const int* in_sizes, int n_in,
                              void* d_out, int out_size)
{
    const float* values = (const float*)d_in[0];
    float* out = (float*)d_out;

    const int tiles = in_sizes[0] / TILE_IN;   // S*N*L = 32000

    powerspectrum_kernel<<<tiles, 128>>>(values, out);
}